// round 11
// baseline (speedup 1.0000x reference)
#include <cuda_runtime.h>

#define NA 24
#define NU 128
#define NV 64
#define NW 128
#define NH 128
#define ND 64
#define NS 128

#define STEP_F 1.5625f            // 2*HS/S = 200/128
#define ELL0   156.0f             // SID - HS
#define ELLST  1.5748031496062993f// 200/127 (linspace endpoint=True)

// filtered sinogram scratch
__device__ float g_filt[NA * NV * NU];

// transposed volume copy: g_volT[z][x][y] = vol[z][y][x]
__device__ float g_volT[ND * NH * NW];

// 4 parity-shifted accumulator volumes of 2x2 (y,x) float4 blocks.
// Volume q = (iy&1)*2 + (ix&1). Slot linear index:
//   addr = ((q*ND + iz)*KB + ky)*KB + kx   (float4 units); z+1 => addr + KB*KB
#define KB 65
__device__ float4 g_acc[4][ND][KB][KB];
#define ZSTRIDE (KB * KB)
// bp only ever touches slot layers iz in [9, 54] (|z - 31.5| <= 21.9)
#define ACC_Z0 9
#define ACC_ZN 46
#define ACC_USED_ELEMS (4 * ACC_ZN * KB * KB)

__device__ __forceinline__ void ray_setup(int a, int u, int v,
                                          float& sx, float& sy,
                                          float& dx, float& dy, float& dz)
{
    double ang = (double)a * (15.0 * 3.14159265358979323846 / 180.0);
    float angf = (float)ang;
    float c = cosf(angf), s = sinf(angf);
    float uu = (float)u - 63.5f;
    float vv = (float)v - 31.5f;
    float ddx = 512.0f * c - uu * s;
    float ddy = 512.0f * s + uu * c;
    float ddz = vv;
    float inv = rsqrtf(ddx * ddx + ddy * ddy + ddz * ddz);
    dx = ddx * inv; dy = ddy * inv; dz = ddz * inv;
    sx = -256.0f * c; sy = -256.0f * s;
}

// ---------------------------------------------------------------------------
// Kernel 0: transpose volume xy (tiled, coalesced both sides)
// ---------------------------------------------------------------------------
__global__ __launch_bounds__(256)
void transpose_kernel(const float* __restrict__ vol)
{
    __shared__ float t[32][33];
    int z = blockIdx.z;
    const float* src = vol + z * (NH * NW);
    float* dst = g_volT + z * (NH * NW);
    int x0 = blockIdx.x * 32, y0 = blockIdx.y * 32;

#pragma unroll
    for (int j = threadIdx.y; j < 32; j += 8)
        t[j][threadIdx.x] = src[(y0 + j) * NW + x0 + threadIdx.x];
    __syncthreads();
#pragma unroll
    for (int j = threadIdx.y; j < 32; j += 8)
        dst[(x0 + j) * NH + y0 + threadIdx.x] = t[threadIdx.x][j];
}

// ---------------------------------------------------------------------------
// Kernel 1: forward project + residual + cosine weight + ramp filter (fused)
// One block = one (a,v) detector row, 128 threads = u.
// ---------------------------------------------------------------------------
__global__ __launch_bounds__(128)
void fp_ramp_kernel(const float* __restrict__ vol, const float* __restrict__ p)
{
    __shared__ float buf[NU];

    int u   = threadIdx.x;
    int row = blockIdx.x;
    int a = row / NV, v = row % NV;

    float sx, sy, dx, dy, dz;
    ray_setup(a, u, v, sx, sy, dx, dy, dz);

    // layout pick: make the lane-varying direction the contiguous dim.
    // u axis = (-sin, cos): lanes spread along x at rate |sin|, along y at |cos|.
    int am = a % 12;                 // |sin|>=|cos| for 15deg*a in [45,135] mod 180
    bool useT = !(am >= 3 && am <= 9);
    const float* V = useT ? g_volT : vol;
    if (useT) {
        float t;
        t = sx; sx = sy; sy = t;
        t = dx; dx = dy; dy = t;
    }

    float sum = 0.0f;
#pragma unroll 4
    for (int i = 0; i < NS; i++) {
        float ell = ELL0 + (float)i * ELLST;
        float cx = fmaf(ell, dx, sx) + 63.5f;   // fast (contiguous) dim
        float cy = fmaf(ell, dy, sy) + 63.5f;   // slow dim
        float cz = ell * dz + 31.5f;

        float fx = floorf(cx), fy = floorf(cy);
        int ix = (int)fx, iy = (int)fy;
        float wx = cx - fx, wy = cy - fy;

        float lx0 = ((unsigned)ix     < NW) ? (1.0f - wx) : 0.0f;
        float lx1 = ((unsigned)(ix+1) < NW) ? wx          : 0.0f;
        float ly0 = ((unsigned)iy     < NH) ? (1.0f - wy) : 0.0f;
        float ly1 = ((unsigned)(iy+1) < NH) ? wy          : 0.0f;
        if ((lx0 == 0.0f && lx1 == 0.0f) || (ly0 == 0.0f && ly1 == 0.0f))
            continue;

        float fz = floorf(cz);
        int iz = (int)fz;
        float wz = cz - fz;

        int ix0 = max(0, min(NW - 1, ix)),  ix1 = max(0, min(NW - 1, ix + 1));
        int iy0 = max(0, min(NH - 1, iy)),  iy1 = max(0, min(NH - 1, iy + 1));

        const float* b0 = V + (size_t)iz * (NH * NW);
        const float* b1 = b0 + (NH * NW);
        float v000 = __ldg(b0 + iy0 * NW + ix0);
        float v001 = __ldg(b0 + iy0 * NW + ix1);
        float v010 = __ldg(b0 + iy1 * NW + ix0);
        float v011 = __ldg(b0 + iy1 * NW + ix1);
        float v100 = __ldg(b1 + iy0 * NW + ix0);
        float v101 = __ldg(b1 + iy0 * NW + ix1);
        float v110 = __ldg(b1 + iy1 * NW + ix0);
        float v111 = __ldg(b1 + iy1 * NW + ix1);

        float p0 = ly0 * (lx0 * v000 + lx1 * v001) + ly1 * (lx0 * v010 + lx1 * v011);
        float p1 = ly0 * (lx0 * v100 + lx1 * v101) + ly1 * (lx0 * v110 + lx1 * v111);
        sum += (1.0f - wz) * p0 + wz * p1;
    }

    // cosine weight uses i - V/2, j - U/2 (integer halves)
    int dv = v - 32, du = u - 64;
    float cw = 512.0f * rsqrtf(512.0f * 512.0f + (float)(dv * dv + du * du));

    buf[u] = (sum * STEP_F - __ldg(&p[row * NU + u])) * cw;
    __syncthreads();

    // Ram-Lak ramp along u (65 nonzero taps), folds adjoint STEP (LAMB=1)
    float acc = 0.125f * buf[u];
#pragma unroll
    for (int d = 1; d <= 63; d += 2) {
        float cf = -0.5f / (9.869604401089358f * (float)(d * d));
        float t = 0.0f;
        int um = u - d; if (um >= 0) t += buf[um];
        int up = u + d; if (up < NU) t += buf[up];
        acc = fmaf(cf, t, acc);
    }
    g_filt[row * NU + u] = acc * STEP_F;
}

// ---------------------------------------------------------------------------
// Kernel 2: zero the touched z-layers of the parity accumulators
// ---------------------------------------------------------------------------
__global__ __launch_bounds__(256)
void zero_acc_kernel()
{
    int i = blockIdx.x * 256 + threadIdx.x;
    if (i < ACC_USED_ELEMS) {
        int q = i / (ACC_ZN * ZSTRIDE);
        int r = i % (ACC_ZN * ZSTRIDE);
        ((float4*)g_acc)[(q * ND + ACC_Z0) * ZSTRIDE + r] =
            make_float4(0.f, 0.f, 0.f, 0.f);
    }
}

// ---------------------------------------------------------------------------
// Kernel 3: adjoint back-projection with warp-segmented atomic merging
// ---------------------------------------------------------------------------
__device__ __forceinline__ void red4(float4* p, float a, float b, float c, float d)
{
    asm volatile("red.global.add.v4.f32 [%0], {%1, %2, %3, %4};"
                 :: "l"(p), "f"(a), "f"(b), "f"(c), "f"(d) : "memory");
}

#define SHALF 32   // samples per block (S split across blockIdx.y)

__global__ __launch_bounds__(128)
void bp_kernel()
{
    int u    = threadIdx.x;
    int lane = u & 31;
    int row  = blockIdx.x;
    int a = row / NV, v = row % NV;
    int i0 = blockIdx.y * SHALF;

    float sx, sy, dx, dy, dz;
    ray_setup(a, u, v, sx, sy, dx, dy, dz);

    float val = __ldg(&g_filt[row * NU + u]);

#pragma unroll 2
    for (int i = i0; i < i0 + SHALF; i++) {
        float ell = ELL0 + (float)i * ELLST;
        float cx = fmaf(ell, dx, sx) + 63.5f;
        float cy = fmaf(ell, dy, sy) + 63.5f;
        float cz = ell * dz + 31.5f;

        bool valid = (cx > -1.0f && cx < 128.0f && cy > -1.0f && cy < 128.0f);
        if (__ballot_sync(0xFFFFFFFFu, valid) == 0u)
            continue;

        unsigned addr = 0xFFFFFFFFu;
        float w0 = 0.f, w1 = 0.f, w2 = 0.f, w3 = 0.f;
        float w4 = 0.f, w5 = 0.f, w6 = 0.f, w7 = 0.f;

        if (valid) {
            float fx = floorf(cx), fy = floorf(cy), fz = floorf(cz);
            int ix = (int)fx, iy = (int)fy, iz = (int)fz;
            float wx = cx - fx, wy = cy - fy, wz = cz - fz;

            int ox = ix & 1, oy = iy & 1;
            int kx = (ix + ox) >> 1, ky = (iy + oy) >> 1;
            int q = oy * 2 + ox;
            addr = (unsigned)(((q * ND + iz) * KB + ky) * KB + kx);

            float t00 = (1.0f - wx) * (1.0f - wy);
            float t01 = wx * (1.0f - wy);
            float t10 = (1.0f - wx) * wy;
            float t11 = wx * wy;
            float vz0 = val * (1.0f - wz);
            float vz1 = val * wz;

            w0 = t00 * vz0; w1 = t01 * vz0; w2 = t10 * vz0; w3 = t11 * vz0;
            w4 = t00 * vz1; w5 = t01 * vz1; w6 = t10 * vz1; w7 = t11 * vz1;
        }

        // segment structure: head lanes + segment end (exclusive) per lane
        unsigned prev = __shfl_up_sync(0xFFFFFFFFu, addr, 1);
        bool head = (lane == 0) || (prev != addr);
        unsigned hb = __ballot_sync(0xFFFFFFFFu, head);
        unsigned above = hb & (0xFFFFFFFEu << lane);            // head bits strictly above
        int next = above ? (__ffs(above) - 1) : 32;             // my segment end
        unsigned below = hb & (0xFFFFFFFFu >> (31 - lane));     // head bits <= lane
        int start = 31 - __clz(below);                          // my segment head

        // 3-step segmented suffix sum (covers 8-lane chunks within a segment)
#pragma unroll
        for (int o = 1; o <= 4; o <<= 1) {
            bool take = (lane + o) < next;
            float t;
            t = __shfl_down_sync(0xFFFFFFFFu, w0, o); if (take) w0 += t;
            t = __shfl_down_sync(0xFFFFFFFFu, w1, o); if (take) w1 += t;
            t = __shfl_down_sync(0xFFFFFFFFu, w2, o); if (take) w2 += t;
            t = __shfl_down_sync(0xFFFFFFFFu, w3, o); if (take) w3 += t;
            t = __shfl_down_sync(0xFFFFFFFFu, w4, o); if (take) w4 += t;
            t = __shfl_down_sync(0xFFFFFFFFu, w5, o); if (take) w5 += t;
            t = __shfl_down_sync(0xFFFFFFFFu, w6, o); if (take) w6 += t;
            t = __shfl_down_sync(0xFFFFFFFFu, w7, o); if (take) w7 += t;
        }

        // one issuer per 8-lane chunk of each segment (handles runs > 8 exactly)
        bool issuer = (((lane - start) & 7) == 0) && (addr != 0xFFFFFFFFu);
        if (issuer) {
            float4* s0 = ((float4*)g_acc) + addr;
            red4(s0,           w0, w1, w2, w3);
            red4(s0 + ZSTRIDE, w4, w5, w6, w7);
        }
    }
}

// ---------------------------------------------------------------------------
// Kernel 4: gather parity accumulators into the output volume
// ---------------------------------------------------------------------------
__global__ __launch_bounds__(128)
void gather_kernel(float* __restrict__ out)
{
    int x  = threadIdx.x;                    // 0..127
    int zy = blockIdx.x;                     // z*NH + y
    int z = zy / NH, y = zy % NH;

    float acc = 0.0f;
    if (z >= ACC_Z0 && z < ACC_Z0 + ACC_ZN) {
#pragma unroll
        for (int oy = 0; oy < 2; oy++) {
            int by = (y + oy) & 1;
            int ky = (y + oy - by) >> 1;
#pragma unroll
            for (int ox = 0; ox < 2; ox++) {
                int bx = (x + ox) & 1;
                int kx = (x + ox - bx) >> 1;
                const float* slot = (const float*)&g_acc[oy * 2 + ox][z][ky][kx];
                acc += __ldg(slot + by * 2 + bx);
            }
        }
    }
    out[zy * NW + x] = acc;
}

// ---------------------------------------------------------------------------
extern "C" void kernel_launch(void* const* d_in, const int* in_sizes, int n_in,
                              void* d_out, int out_size)
{
    const float* x = (const float*)d_in[0];   // [1,1,D,H,W]
    const float* p = (const float*)d_in[1];   // [1,1,A,V,U]
    float* out = (float*)d_out;               // [1,1,D,H,W]

    transpose_kernel<<<dim3(4, 4, ND), dim3(32, 8)>>>(x);
    zero_acc_kernel<<<(ACC_USED_ELEMS + 255) / 256, 256>>>();
    fp_ramp_kernel<<<NA * NV, NU>>>(x, p);
    bp_kernel<<<dim3(NA * NV, NS / SHALF), NU>>>();
    gather_kernel<<<ND * NH, NW>>>(out);
}

// round 12
// speedup vs baseline: 1.6081x; 1.6081x over previous
#include <cuda_runtime.h>

#define NA 24
#define NU 128
#define NV 64
#define NW 128
#define NH 128
#define ND 64
#define NS 128

#define STEP_F 1.5625f            // 2*HS/S = 200/128
#define ELL0   156.0f             // SID - HS
#define ELLST  1.5748031496062993f// 200/127 (linspace endpoint=True)

// transposed volume copy: g_volT[z][x][y] = vol[z][y][x]
__device__ float g_volT[ND * NH * NW];

// 4 parity-shifted accumulator volumes of 2x2 (y,x) float4 blocks.
// Volume q = (iy&1)*2 + (ix&1). Slot linear index:
//   addr = ((q*ND + iz)*KB + ky)*KB + kx   (float4 units); z+1 => addr + KB*KB
#define KB 65
__device__ float4 g_acc[4][ND][KB][KB];
#define ZSTRIDE (KB * KB)
// bp only ever touches slot layers iz in [9, 54] (|z - 31.5| <= 21.9)
#define ACC_Z0 9
#define ACC_ZN 46
#define ACC_USED_ELEMS (4 * ACC_ZN * KB * KB)

__device__ __forceinline__ void ray_setup(int a, int u, int v,
                                          float& sx, float& sy,
                                          float& dx, float& dy, float& dz)
{
    double ang = (double)a * (15.0 * 3.14159265358979323846 / 180.0);
    float angf = (float)ang;
    float c = cosf(angf), s = sinf(angf);
    float uu = (float)u - 63.5f;
    float vv = (float)v - 31.5f;
    float ddx = 512.0f * c - uu * s;
    float ddy = 512.0f * s + uu * c;
    float ddz = vv;
    float inv = rsqrtf(ddx * ddx + ddy * ddy + ddz * ddz);
    dx = ddx * inv; dy = ddy * inv; dz = ddz * inv;
    sx = -256.0f * c; sy = -256.0f * s;
}

// ---------------------------------------------------------------------------
// Kernel 0: transpose volume xy (tiled, coalesced both sides)
// ---------------------------------------------------------------------------
__global__ __launch_bounds__(256)
void transpose_kernel(const float* __restrict__ vol)
{
    __shared__ float t[32][33];
    int z = blockIdx.z;
    const float* src = vol + z * (NH * NW);
    float* dst = g_volT + z * (NH * NW);
    int x0 = blockIdx.x * 32, y0 = blockIdx.y * 32;

#pragma unroll
    for (int j = threadIdx.y; j < 32; j += 8)
        t[j][threadIdx.x] = src[(y0 + j) * NW + x0 + threadIdx.x];
    __syncthreads();
#pragma unroll
    for (int j = threadIdx.y; j < 32; j += 8)
        dst[(x0 + j) * NH + y0 + threadIdx.x] = t[threadIdx.x][j];
}

// ---------------------------------------------------------------------------
// Kernel 1: zero the touched z-layers of the parity accumulators
// ---------------------------------------------------------------------------
__global__ __launch_bounds__(256)
void zero_acc_kernel()
{
    int i = blockIdx.x * 256 + threadIdx.x;
    if (i < ACC_USED_ELEMS) {
        int q = i / (ACC_ZN * ZSTRIDE);
        int r = i % (ACC_ZN * ZSTRIDE);
        ((float4*)g_acc)[(q * ND + ACC_Z0) * ZSTRIDE + r] =
            make_float4(0.f, 0.f, 0.f, 0.f);
    }
}

// ---------------------------------------------------------------------------
// Kernel 2: FUSED  forward-project + residual + cosine + ramp + back-project
// One block = one (a,v) detector row, 128 threads = u.
// ---------------------------------------------------------------------------
__device__ __forceinline__ void red4(float4* p, float a, float b, float c, float d)
{
    asm volatile("red.global.add.v4.f32 [%0], {%1, %2, %3, %4};"
                 :: "l"(p), "f"(a), "f"(b), "f"(c), "f"(d) : "memory");
}

__global__ __launch_bounds__(128)
void fbp_kernel(const float* __restrict__ vol, const float* __restrict__ p)
{
    __shared__ float buf[NU];

    int u    = threadIdx.x;
    int lane = u & 31;
    int row  = blockIdx.x;
    int a = row / NV, v = row % NV;

    float sx, sy, dx, dy, dz;
    ray_setup(a, u, v, sx, sy, dx, dy, dz);

    // ---- Phase 1: forward projection (layout-adaptive gathers) ----
    // u axis = (-sin, cos): lanes spread along x at rate |sin|, along y at |cos|.
    int am = a % 12;                 // |sin|>=|cos| for 15deg*a in [45,135] mod 180
    bool useT = !(am >= 3 && am <= 9);
    const float* V = useT ? g_volT : vol;
    float fsx = useT ? sy : sx, fsy = useT ? sx : sy;
    float fdx = useT ? dy : dx, fdy = useT ? dx : dy;

    float sum = 0.0f;
#pragma unroll 4
    for (int i = 0; i < NS; i++) {
        float ell = ELL0 + (float)i * ELLST;
        float cx = fmaf(ell, fdx, fsx) + 63.5f;   // fast (contiguous) dim
        float cy = fmaf(ell, fdy, fsy) + 63.5f;   // slow dim
        float cz = ell * dz + 31.5f;

        float fx = floorf(cx), fy = floorf(cy);
        int ix = (int)fx, iy = (int)fy;
        float wx = cx - fx, wy = cy - fy;

        float lx0 = ((unsigned)ix     < NW) ? (1.0f - wx) : 0.0f;
        float lx1 = ((unsigned)(ix+1) < NW) ? wx          : 0.0f;
        float ly0 = ((unsigned)iy     < NH) ? (1.0f - wy) : 0.0f;
        float ly1 = ((unsigned)(iy+1) < NH) ? wy          : 0.0f;
        if ((lx0 == 0.0f && lx1 == 0.0f) || (ly0 == 0.0f && ly1 == 0.0f))
            continue;

        float fz = floorf(cz);
        int iz = (int)fz;
        float wz = cz - fz;

        int ix0 = max(0, min(NW - 1, ix)),  ix1 = max(0, min(NW - 1, ix + 1));
        int iy0 = max(0, min(NH - 1, iy)),  iy1 = max(0, min(NH - 1, iy + 1));

        const float* b0 = V + (size_t)iz * (NH * NW);
        const float* b1 = b0 + (NH * NW);
        float v000 = __ldg(b0 + iy0 * NW + ix0);
        float v001 = __ldg(b0 + iy0 * NW + ix1);
        float v010 = __ldg(b0 + iy1 * NW + ix0);
        float v011 = __ldg(b0 + iy1 * NW + ix1);
        float v100 = __ldg(b1 + iy0 * NW + ix0);
        float v101 = __ldg(b1 + iy0 * NW + ix1);
        float v110 = __ldg(b1 + iy1 * NW + ix0);
        float v111 = __ldg(b1 + iy1 * NW + ix1);

        float p0 = ly0 * (lx0 * v000 + lx1 * v001) + ly1 * (lx0 * v010 + lx1 * v011);
        float p1 = ly0 * (lx0 * v100 + lx1 * v101) + ly1 * (lx0 * v110 + lx1 * v111);
        sum += (1.0f - wz) * p0 + wz * p1;
    }

    // cosine weight uses i - V/2, j - U/2 (integer halves)
    int dv = v - 32, du = u - 64;
    float cw = 512.0f * rsqrtf(512.0f * 512.0f + (float)(dv * dv + du * du));

    buf[u] = (sum * STEP_F - __ldg(&p[row * NU + u])) * cw;
    __syncthreads();

    // ---- Phase 2: Ram-Lak ramp along u (65 nonzero taps), folds STEP ----
    float acc = 0.125f * buf[u];
#pragma unroll
    for (int d = 1; d <= 63; d += 2) {
        float cf = -0.5f / (9.869604401089358f * (float)(d * d));
        float t = 0.0f;
        int um = u - d; if (um >= 0) t += buf[um];
        int up = u + d; if (up < NU) t += buf[up];
        acc = fmaf(cf, t, acc);
    }
    float val = acc * STEP_F;    // filtered value, stays in register

    // ---- Phase 3: adjoint scatter with warp-segmented atomic merging ----
#pragma unroll 2
    for (int i = 0; i < NS; i++) {
        float ell = ELL0 + (float)i * ELLST;
        float cx = fmaf(ell, dx, sx) + 63.5f;
        float cy = fmaf(ell, dy, sy) + 63.5f;
        float cz = ell * dz + 31.5f;

        bool valid = (cx > -1.0f && cx < 128.0f && cy > -1.0f && cy < 128.0f);
        if (__ballot_sync(0xFFFFFFFFu, valid) == 0u)
            continue;

        unsigned addr = 0xFFFFFFFFu;
        float w0 = 0.f, w1 = 0.f, w2 = 0.f, w3 = 0.f;
        float w4 = 0.f, w5 = 0.f, w6 = 0.f, w7 = 0.f;

        if (valid) {
            float fx = floorf(cx), fy = floorf(cy), fz = floorf(cz);
            int ix = (int)fx, iy = (int)fy, iz = (int)fz;
            float wx = cx - fx, wy = cy - fy, wz = cz - fz;

            int ox = ix & 1, oy = iy & 1;
            int kx = (ix + ox) >> 1, ky = (iy + oy) >> 1;
            int q = oy * 2 + ox;
            addr = (unsigned)(((q * ND + iz) * KB + ky) * KB + kx);

            float t00 = (1.0f - wx) * (1.0f - wy);
            float t01 = wx * (1.0f - wy);
            float t10 = (1.0f - wx) * wy;
            float t11 = wx * wy;
            float vz0 = val * (1.0f - wz);
            float vz1 = val * wz;

            w0 = t00 * vz0; w1 = t01 * vz0; w2 = t10 * vz0; w3 = t11 * vz0;
            w4 = t00 * vz1; w5 = t01 * vz1; w6 = t10 * vz1; w7 = t11 * vz1;
        }

        // segment structure: head lanes + segment end (exclusive) per lane
        unsigned prev = __shfl_up_sync(0xFFFFFFFFu, addr, 1);
        bool head = (lane == 0) || (prev != addr);
        unsigned hb = __ballot_sync(0xFFFFFFFFu, head);
        unsigned above = hb & (0xFFFFFFFEu << lane);            // head bits strictly above
        int next = above ? (__ffs(above) - 1) : 32;             // my segment end
        unsigned below = hb & (0xFFFFFFFFu >> (31 - lane));     // head bits <= lane
        int start = 31 - __clz(below);                          // my segment head

        // 3-step segmented suffix sum (covers 8-lane chunks within a segment)
#pragma unroll
        for (int o = 1; o <= 4; o <<= 1) {
            bool take = (lane + o) < next;
            float t;
            t = __shfl_down_sync(0xFFFFFFFFu, w0, o); if (take) w0 += t;
            t = __shfl_down_sync(0xFFFFFFFFu, w1, o); if (take) w1 += t;
            t = __shfl_down_sync(0xFFFFFFFFu, w2, o); if (take) w2 += t;
            t = __shfl_down_sync(0xFFFFFFFFu, w3, o); if (take) w3 += t;
            t = __shfl_down_sync(0xFFFFFFFFu, w4, o); if (take) w4 += t;
            t = __shfl_down_sync(0xFFFFFFFFu, w5, o); if (take) w5 += t;
            t = __shfl_down_sync(0xFFFFFFFFu, w6, o); if (take) w6 += t;
            t = __shfl_down_sync(0xFFFFFFFFu, w7, o); if (take) w7 += t;
        }

        // one issuer per 8-lane chunk of each segment (handles runs > 8 exactly)
        bool issuer = (((lane - start) & 7) == 0) && (addr != 0xFFFFFFFFu);
        if (issuer) {
            float4* s0 = ((float4*)g_acc) + addr;
            red4(s0,           w0, w1, w2, w3);
            red4(s0 + ZSTRIDE, w4, w5, w6, w7);
        }
    }
}

// ---------------------------------------------------------------------------
// Kernel 3: gather parity accumulators into the output volume
// ---------------------------------------------------------------------------
__global__ __launch_bounds__(128)
void gather_kernel(float* __restrict__ out)
{
    int x  = threadIdx.x;                    // 0..127
    int zy = blockIdx.x;                     // z*NH + y
    int z = zy / NH, y = zy % NH;

    float acc = 0.0f;
    if (z >= ACC_Z0 && z < ACC_Z0 + ACC_ZN) {
#pragma unroll
        for (int oy = 0; oy < 2; oy++) {
            int by = (y + oy) & 1;
            int ky = (y + oy - by) >> 1;
#pragma unroll
            for (int ox = 0; ox < 2; ox++) {
                int bx = (x + ox) & 1;
                int kx = (x + ox - bx) >> 1;
                const float* slot = (const float*)&g_acc[oy * 2 + ox][z][ky][kx];
                acc += __ldg(slot + by * 2 + bx);
            }
        }
    }
    out[zy * NW + x] = acc;
}

// ---------------------------------------------------------------------------
extern "C" void kernel_launch(void* const* d_in, const int* in_sizes, int n_in,
                              void* d_out, int out_size)
{
    const float* x = (const float*)d_in[0];   // [1,1,D,H,W]
    const float* p = (const float*)d_in[1];   // [1,1,A,V,U]
    float* out = (float*)d_out;               // [1,1,D,H,W]

    transpose_kernel<<<dim3(4, 4, ND), dim3(32, 8)>>>(x);
    zero_acc_kernel<<<(ACC_USED_ELEMS + 255) / 256, 256>>>();
    fbp_kernel<<<NA * NV, NU>>>(x, p);
    gather_kernel<<<ND * NH, NW>>>(out);
}

// round 16
// speedup vs baseline: 1.6167x; 1.0053x over previous
#include <cuda_runtime.h>

#define NA 24
#define NU 128
#define NV 64
#define NW 128
#define NH 128
#define ND 64
#define NS 128

#define STEP_F 1.5625f            // 2*HS/S = 200/128
#define ELL0   156.0f             // SID - HS
#define ELLST  1.5748031496062993f// 200/127 (linspace endpoint=True)
#define INV_ELLST 0.635f          // 1/ELLST (only used for loop-bound estimate)

// transposed volume copy: g_volT[z][x][y] = vol[z][y][x]
__device__ float g_volT[ND * NH * NW];

// 4 parity-shifted accumulator volumes of 2x2 (y,x) float4 blocks.
// Volume q = (iy&1)*2 + (ix&1). Slot linear index:
//   addr = ((q*ND + iz)*KB + ky)*KB + kx   (float4 units); z+1 => addr + KB*KB
#define KB 65
__device__ float4 g_acc[4][ND][KB][KB];
#define ZSTRIDE (KB * KB)
// bp only ever touches slot layers iz in [9, 54] (|z - 31.5| <= 21.9)
#define ACC_Z0 9
#define ACC_ZN 46
#define ACC_USED_ELEMS (4 * ACC_ZN * KB * KB)

__device__ __forceinline__ void ray_setup(int a, int u, int v,
                                          float& sx, float& sy,
                                          float& dx, float& dy, float& dz)
{
    double ang = (double)a * (15.0 * 3.14159265358979323846 / 180.0);
    float angf = (float)ang;
    float c = cosf(angf), s = sinf(angf);
    float uu = (float)u - 63.5f;
    float vv = (float)v - 31.5f;
    float ddx = 512.0f * c - uu * s;
    float ddy = 512.0f * s + uu * c;
    float ddz = vv;
    float inv = rsqrtf(ddx * ddx + ddy * ddy + ddz * ddz);
    dx = ddx * inv; dy = ddy * inv; dz = ddz * inv;
    sx = -256.0f * c; sy = -256.0f * s;
}

// ell-interval where off + ell*d lies in (-1, 128); updates [lmin, lmax]
__device__ __forceinline__ void clip_axis(float off, float d,
                                          float& lmin, float& lmax)
{
    if (fabsf(d) > 1e-6f) {
        float ra = (-1.0f - off) / d;
        float rb = (128.0f - off) / d;
        lmin = fmaxf(lmin, fminf(ra, rb));
        lmax = fminf(lmax, fmaxf(ra, rb));
    } else if (off <= -1.0f || off >= 128.0f) {
        lmin = 1e30f; lmax = -1e30f;   // empty
    }
}

// ---------------------------------------------------------------------------
// Kernel 0: transpose volume xy (tiled, coalesced both sides)
// ---------------------------------------------------------------------------
__global__ __launch_bounds__(256)
void transpose_kernel(const float* __restrict__ vol)
{
    __shared__ float t[32][33];
    int z = blockIdx.z;
    const float* src = vol + z * (NH * NW);
    float* dst = g_volT + z * (NH * NW);
    int x0 = blockIdx.x * 32, y0 = blockIdx.y * 32;

#pragma unroll
    for (int j = threadIdx.y; j < 32; j += 8)
        t[j][threadIdx.x] = src[(y0 + j) * NW + x0 + threadIdx.x];
    __syncthreads();
#pragma unroll
    for (int j = threadIdx.y; j < 32; j += 8)
        dst[(x0 + j) * NH + y0 + threadIdx.x] = t[threadIdx.x][j];
}

// ---------------------------------------------------------------------------
// Kernel 1: zero the touched z-layers of the parity accumulators
// ---------------------------------------------------------------------------
__global__ __launch_bounds__(256)
void zero_acc_kernel()
{
    int i = blockIdx.x * 256 + threadIdx.x;
    if (i < ACC_USED_ELEMS) {
        int q = i / (ACC_ZN * ZSTRIDE);
        int r = i % (ACC_ZN * ZSTRIDE);
        ((float4*)g_acc)[(q * ND + ACC_Z0) * ZSTRIDE + r] =
            make_float4(0.f, 0.f, 0.f, 0.f);
    }
}

// ---------------------------------------------------------------------------
// Kernel 2: FUSED  forward-project + residual + cosine + ramp + back-project
// One block = one (a,v) detector row, 128 threads = u.
// ---------------------------------------------------------------------------
__device__ __forceinline__ void red4(float4* p, float a, float b, float c, float d)
{
    asm volatile("red.global.add.v4.f32 [%0], {%1, %2, %3, %4};"
                 :: "l"(p), "f"(a), "f"(b), "f"(c), "f"(d) : "memory");
}

__global__ __launch_bounds__(128)
void fbp_kernel(const float* __restrict__ vol, const float* __restrict__ p)
{
    __shared__ float buf[NU];

    int u    = threadIdx.x;
    int lane = u & 31;
    int row  = blockIdx.x;
    int a = row / NV, v = row % NV;

    float sx, sy, dx, dy, dz;
    ray_setup(a, u, v, sx, sy, dx, dy, dz);

    // ---- active sample interval: ell where both cx,cy in (-1,128) ----
    // (widened by 1 sample each side; exact per-sample guards stay in place)
    float lmin = ELL0, lmax = ELL0 + 127.0f * ELLST;
    clip_axis(sx + 63.5f, dx, lmin, lmax);
    clip_axis(sy + 63.5f, dy, lmin, lmax);
    int iLo, iHi;
    if (lmin > lmax) { iLo = 0; iHi = 0; }
    else {
        iLo = max(0,  (int)floorf((lmin - ELL0) * INV_ELLST) - 1);
        iHi = min(NS, (int)ceilf ((lmax - ELL0) * INV_ELLST) + 2);
    }
    // warp-union bounds (bp scan needs full-warp participation)
    int iLoW = __reduce_min_sync(0xFFFFFFFFu, iLo);
    int iHiW = __reduce_max_sync(0xFFFFFFFFu, iHi);

    // ---- Phase 1: forward projection (layout-adaptive gathers) ----
    int am = a % 12;                 // |sin|>=|cos| for 15deg*a in [45,135] mod 180
    bool useT = !(am >= 3 && am <= 9);
    const float* V = useT ? g_volT : vol;
    float fsx = useT ? sy : sx, fsy = useT ? sx : sy;
    float fdx = useT ? dy : dx, fdy = useT ? dx : dy;

    float sum = 0.0f;
#pragma unroll 4
    for (int i = iLoW; i < iHiW; i++) {
        float ell = ELL0 + (float)i * ELLST;
        float cx = fmaf(ell, fdx, fsx) + 63.5f;   // fast (contiguous) dim
        float cy = fmaf(ell, fdy, fsy) + 63.5f;   // slow dim
        float cz = ell * dz + 31.5f;

        float fx = floorf(cx), fy = floorf(cy);
        int ix = (int)fx, iy = (int)fy;
        float wx = cx - fx, wy = cy - fy;

        float lx0 = ((unsigned)ix     < NW) ? (1.0f - wx) : 0.0f;
        float lx1 = ((unsigned)(ix+1) < NW) ? wx          : 0.0f;
        float ly0 = ((unsigned)iy     < NH) ? (1.0f - wy) : 0.0f;
        float ly1 = ((unsigned)(iy+1) < NH) ? wy          : 0.0f;
        if ((lx0 == 0.0f && lx1 == 0.0f) || (ly0 == 0.0f && ly1 == 0.0f))
            continue;

        float fz = floorf(cz);
        int iz = (int)fz;
        float wz = cz - fz;

        int ix0 = max(0, min(NW - 1, ix)),  ix1 = max(0, min(NW - 1, ix + 1));
        int iy0 = max(0, min(NH - 1, iy)),  iy1 = max(0, min(NH - 1, iy + 1));

        const float* b0 = V + (size_t)iz * (NH * NW);
        const float* b1 = b0 + (NH * NW);
        float v000 = __ldg(b0 + iy0 * NW + ix0);
        float v001 = __ldg(b0 + iy0 * NW + ix1);
        float v010 = __ldg(b0 + iy1 * NW + ix0);
        float v011 = __ldg(b0 + iy1 * NW + ix1);
        float v100 = __ldg(b1 + iy0 * NW + ix0);
        float v101 = __ldg(b1 + iy0 * NW + ix1);
        float v110 = __ldg(b1 + iy1 * NW + ix0);
        float v111 = __ldg(b1 + iy1 * NW + ix1);

        float p0 = ly0 * (lx0 * v000 + lx1 * v001) + ly1 * (lx0 * v010 + lx1 * v011);
        float p1 = ly0 * (lx0 * v100 + lx1 * v101) + ly1 * (lx0 * v110 + lx1 * v111);
        sum += (1.0f - wz) * p0 + wz * p1;
    }

    // cosine weight uses i - V/2, j - U/2 (integer halves)
    int dv = v - 32, du = u - 64;
    float cw = 512.0f * rsqrtf(512.0f * 512.0f + (float)(dv * dv + du * du));

    buf[u] = (sum * STEP_F - __ldg(&p[row * NU + u])) * cw;
    __syncthreads();

    // ---- Phase 2: Ram-Lak ramp along u (65 nonzero taps), folds STEP ----
    float acc = 0.125f * buf[u];
#pragma unroll
    for (int d = 1; d <= 63; d += 2) {
        float cf = -0.5f / (9.869604401089358f * (float)(d * d));
        float t = 0.0f;
        int um = u - d; if (um >= 0) t += buf[um];
        int up = u + d; if (up < NU) t += buf[up];
        acc = fmaf(cf, t, acc);
    }
    float val = acc * STEP_F;    // filtered value, stays in register

    // ---- Phase 3: adjoint scatter with warp-segmented atomic merging ----
#pragma unroll 2
    for (int i = iLoW; i < iHiW; i++) {
        float ell = ELL0 + (float)i * ELLST;
        float cx = fmaf(ell, dx, sx) + 63.5f;
        float cy = fmaf(ell, dy, sy) + 63.5f;
        float cz = ell * dz + 31.5f;

        bool valid = (cx > -1.0f && cx < 128.0f && cy > -1.0f && cy < 128.0f);

        unsigned addr = 0xFFFFFFFFu;
        float w0 = 0.f, w1 = 0.f, w2 = 0.f, w3 = 0.f;
        float w4 = 0.f, w5 = 0.f, w6 = 0.f, w7 = 0.f;

        if (valid) {
            float fx = floorf(cx), fy = floorf(cy), fz = floorf(cz);
            int ix = (int)fx, iy = (int)fy, iz = (int)fz;
            float wx = cx - fx, wy = cy - fy, wz = cz - fz;

            int ox = ix & 1, oy = iy & 1;
            int kx = (ix + ox) >> 1, ky = (iy + oy) >> 1;
            int q = oy * 2 + ox;
            addr = (unsigned)(((q * ND + iz) * KB + ky) * KB + kx);

            float t00 = (1.0f - wx) * (1.0f - wy);
            float t01 = wx * (1.0f - wy);
            float t10 = (1.0f - wx) * wy;
            float t11 = wx * wy;
            float vz0 = val * (1.0f - wz);
            float vz1 = val * wz;

            w0 = t00 * vz0; w1 = t01 * vz0; w2 = t10 * vz0; w3 = t11 * vz0;
            w4 = t00 * vz1; w5 = t01 * vz1; w6 = t10 * vz1; w7 = t11 * vz1;
        }

        // segment structure: head lanes + segment end (exclusive) per lane
        unsigned prev = __shfl_up_sync(0xFFFFFFFFu, addr, 1);
        bool head = (lane == 0) || (prev != addr);
        unsigned hb = __ballot_sync(0xFFFFFFFFu, head);
        unsigned above = hb & (0xFFFFFFFEu << lane);            // head bits strictly above
        int next = above ? (__ffs(above) - 1) : 32;             // my segment end
        unsigned below = hb & (0xFFFFFFFFu >> (31 - lane));     // head bits <= lane
        int start = 31 - __clz(below);                          // my segment head

        // 3-step segmented suffix sum (covers 8-lane chunks within a segment)
#pragma unroll
        for (int o = 1; o <= 4; o <<= 1) {
            bool take = (lane + o) < next;
            float t;
            t = __shfl_down_sync(0xFFFFFFFFu, w0, o); if (take) w0 += t;
            t = __shfl_down_sync(0xFFFFFFFFu, w1, o); if (take) w1 += t;
            t = __shfl_down_sync(0xFFFFFFFFu, w2, o); if (take) w2 += t;
            t = __shfl_down_sync(0xFFFFFFFFu, w3, o); if (take) w3 += t;
            t = __shfl_down_sync(0xFFFFFFFFu, w4, o); if (take) w4 += t;
            t = __shfl_down_sync(0xFFFFFFFFu, w5, o); if (take) w5 += t;
            t = __shfl_down_sync(0xFFFFFFFFu, w6, o); if (take) w6 += t;
            t = __shfl_down_sync(0xFFFFFFFFu, w7, o); if (take) w7 += t;
        }

        // one issuer per 8-lane chunk of each segment (handles runs > 8 exactly)
        bool issuer = (((lane - start) & 7) == 0) && (addr != 0xFFFFFFFFu);
        if (issuer) {
            float4* s0 = ((float4*)g_acc) + addr;
            red4(s0,           w0, w1, w2, w3);
            red4(s0 + ZSTRIDE, w4, w5, w6, w7);
        }
    }
}

// ---------------------------------------------------------------------------
// Kernel 3: gather parity accumulators into the output volume
// ---------------------------------------------------------------------------
__global__ __launch_bounds__(128)
void gather_kernel(float* __restrict__ out)
{
    int x  = threadIdx.x;                    // 0..127
    int zy = blockIdx.x;                     // z*NH + y
    int z = zy / NH, y = zy % NH;

    float acc = 0.0f;
    if (z >= ACC_Z0 && z < ACC_Z0 + ACC_ZN) {
#pragma unroll
        for (int oy = 0; oy < 2; oy++) {
            int by = (y + oy) & 1;
            int ky = (y + oy - by) >> 1;
#pragma unroll
            for (int ox = 0; ox < 2; ox++) {
                int bx = (x + ox) & 1;
                int kx = (x + ox - bx) >> 1;
                const float* slot = (const float*)&g_acc[oy * 2 + ox][z][ky][kx];
                acc += __ldg(slot + by * 2 + bx);
            }
        }
    }
    out[zy * NW + x] = acc;
}

// ---------------------------------------------------------------------------
extern "C" void kernel_launch(void* const* d_in, const int* in_sizes, int n_in,
                              void* d_out, int out_size)
{
    const float* x = (const float*)d_in[0];   // [1,1,D,H,W]
    const float* p = (const float*)d_in[1];   // [1,1,A,V,U]
    float* out = (float*)d_out;               // [1,1,D,H,W]

    transpose_kernel<<<dim3(4, 4, ND), dim3(32, 8)>>>(x);
    zero_acc_kernel<<<(ACC_USED_ELEMS + 255) / 256, 256>>>();
    fbp_kernel<<<NA * NV, NU>>>(x, p);
    gather_kernel<<<ND * NH, NW>>>(out);
}

// round 17
// speedup vs baseline: 1.6541x; 1.0231x over previous
#include <cuda_runtime.h>

#define NA 24
#define NU 128
#define NV 64
#define NW 128
#define NH 128
#define ND 64
#define NS 128

#define STEP_F 1.5625f            // 2*HS/S = 200/128
#define ELL0   156.0f             // SID - HS
#define ELLST  1.5748031496062993f// 200/127 (linspace endpoint=True)

// transposed volume copy: g_volT[z][x][y] = vol[z][y][x]
__device__ float g_volT[ND * NH * NW];

// 4 parity-shifted accumulator volumes of 2x2 (y,x) float4 blocks.
// Volume q = (iy&1)*2 + (ix&1). Slot linear index:
//   addr = ((q*ND + iz)*KB + ky)*KB + kx   (float4 units); z+1 => addr + KB*KB
#define KB 65
__device__ float4 g_acc[4][ND][KB][KB];
#define ZSTRIDE (KB * KB)
// bp only ever touches slot layers iz in [9, 54] (|z - 31.5| <= 21.9)
#define ACC_Z0 9
#define ACC_ZN 46
#define ACC_USED_ELEMS (4 * ACC_ZN * KB * KB)

__device__ __forceinline__ void ray_setup(int a, int u, int v,
                                          float& sx, float& sy,
                                          float& dx, float& dy, float& dz)
{
    double ang = (double)a * (15.0 * 3.14159265358979323846 / 180.0);
    float angf = (float)ang;
    float c = cosf(angf), s = sinf(angf);
    float uu = (float)u - 63.5f;
    float vv = (float)v - 31.5f;
    float ddx = 512.0f * c - uu * s;
    float ddy = 512.0f * s + uu * c;
    float ddz = vv;
    float inv = rsqrtf(ddx * ddx + ddy * ddy + ddz * ddz);
    dx = ddx * inv; dy = ddy * inv; dz = ddz * inv;
    sx = -256.0f * c; sy = -256.0f * s;
}

// ---------------------------------------------------------------------------
// Kernel 0: transpose volume xy (tiled, coalesced both sides)
// ---------------------------------------------------------------------------
__global__ __launch_bounds__(256)
void transpose_kernel(const float* __restrict__ vol)
{
    __shared__ float t[32][33];
    int z = blockIdx.z;
    const float* src = vol + z * (NH * NW);
    float* dst = g_volT + z * (NH * NW);
    int x0 = blockIdx.x * 32, y0 = blockIdx.y * 32;

#pragma unroll
    for (int j = threadIdx.y; j < 32; j += 8)
        t[j][threadIdx.x] = src[(y0 + j) * NW + x0 + threadIdx.x];
    __syncthreads();
#pragma unroll
    for (int j = threadIdx.y; j < 32; j += 8)
        dst[(x0 + j) * NH + y0 + threadIdx.x] = t[threadIdx.x][j];
}

// ---------------------------------------------------------------------------
// Kernel 1: zero the touched z-layers of the parity accumulators
// ---------------------------------------------------------------------------
__global__ __launch_bounds__(256)
void zero_acc_kernel()
{
    int i = blockIdx.x * 256 + threadIdx.x;
    if (i < ACC_USED_ELEMS) {
        int q = i / (ACC_ZN * ZSTRIDE);
        int r = i % (ACC_ZN * ZSTRIDE);
        ((float4*)g_acc)[(q * ND + ACC_Z0) * ZSTRIDE + r] =
            make_float4(0.f, 0.f, 0.f, 0.f);
    }
}

// ---------------------------------------------------------------------------
// Kernel 2: FUSED  forward-project + residual + cosine + ramp + back-project
// One block = one (a,v) detector row, 128 threads = u.
// ---------------------------------------------------------------------------
__device__ __forceinline__ void red4(float4* p, float a, float b, float c, float d)
{
    asm volatile("red.global.add.v4.f32 [%0], {%1, %2, %3, %4};"
                 :: "l"(p), "f"(a), "f"(b), "f"(c), "f"(d) : "memory");
}

__global__ __launch_bounds__(128)
void fbp_kernel(const float* __restrict__ vol, const float* __restrict__ p)
{
    __shared__ float buf[NU];

    int u    = threadIdx.x;
    int lane = u & 31;
    int row  = blockIdx.x;
    int a = row / NV, v = row % NV;

    float sx, sy, dx, dy, dz;
    ray_setup(a, u, v, sx, sy, dx, dy, dz);

    // ---- Phase 1: forward projection (layout-adaptive gathers) ----
    int am = a % 12;                 // |sin|>=|cos| for 15deg*a in [45,135] mod 180
    bool useT = !(am >= 3 && am <= 9);
    const float* V = useT ? g_volT : vol;
    float fsx = useT ? sy : sx, fsy = useT ? sx : sy;
    float fdx = useT ? dy : dx, fdy = useT ? dx : dy;

    float sum = 0.0f;
#pragma unroll 4
    for (int i = 0; i < NS; i++) {
        float ell = ELL0 + (float)i * ELLST;
        float cx = fmaf(ell, fdx, fsx) + 63.5f;   // fast (contiguous) dim
        float cy = fmaf(ell, fdy, fsy) + 63.5f;   // slow dim
        float cz = ell * dz + 31.5f;

        float fx = floorf(cx), fy = floorf(cy);
        int ix = (int)fx, iy = (int)fy;
        float wx = cx - fx, wy = cy - fy;

        float lx0 = ((unsigned)ix     < NW) ? (1.0f - wx) : 0.0f;
        float lx1 = ((unsigned)(ix+1) < NW) ? wx          : 0.0f;
        float ly0 = ((unsigned)iy     < NH) ? (1.0f - wy) : 0.0f;
        float ly1 = ((unsigned)(iy+1) < NH) ? wy          : 0.0f;
        if ((lx0 == 0.0f && lx1 == 0.0f) || (ly0 == 0.0f && ly1 == 0.0f))
            continue;

        float fz = floorf(cz);
        int iz = (int)fz;
        float wz = cz - fz;

        int ix0 = max(0, min(NW - 1, ix)),  ix1 = max(0, min(NW - 1, ix + 1));
        int iy0 = max(0, min(NH - 1, iy)),  iy1 = max(0, min(NH - 1, iy + 1));

        const float* b0 = V + (size_t)iz * (NH * NW);
        const float* b1 = b0 + (NH * NW);
        float v000 = __ldg(b0 + iy0 * NW + ix0);
        float v001 = __ldg(b0 + iy0 * NW + ix1);
        float v010 = __ldg(b0 + iy1 * NW + ix0);
        float v011 = __ldg(b0 + iy1 * NW + ix1);
        float v100 = __ldg(b1 + iy0 * NW + ix0);
        float v101 = __ldg(b1 + iy0 * NW + ix1);
        float v110 = __ldg(b1 + iy1 * NW + ix0);
        float v111 = __ldg(b1 + iy1 * NW + ix1);

        float p0 = ly0 * (lx0 * v000 + lx1 * v001) + ly1 * (lx0 * v010 + lx1 * v011);
        float p1 = ly0 * (lx0 * v100 + lx1 * v101) + ly1 * (lx0 * v110 + lx1 * v111);
        sum += (1.0f - wz) * p0 + wz * p1;
    }

    // cosine weight uses i - V/2, j - U/2 (integer halves)
    int dv = v - 32, du = u - 64;
    float cw = 512.0f * rsqrtf(512.0f * 512.0f + (float)(dv * dv + du * du));

    buf[u] = (sum * STEP_F - __ldg(&p[row * NU + u])) * cw;
    __syncthreads();

    // ---- Phase 2: Ram-Lak ramp along u (65 nonzero taps), folds STEP ----
    float acc = 0.125f * buf[u];
#pragma unroll
    for (int d = 1; d <= 63; d += 2) {
        float cf = -0.5f / (9.869604401089358f * (float)(d * d));
        float t = 0.0f;
        int um = u - d; if (um >= 0) t += buf[um];
        int up = u + d; if (up < NU) t += buf[up];
        acc = fmaf(cf, t, acc);
    }
    float val = acc * STEP_F;    // filtered value, stays in register

    // ---- Phase 3: adjoint scatter, merge-4 segmented (SHFL-light) ----
#pragma unroll 2
    for (int i = 0; i < NS; i++) {
        float ell = ELL0 + (float)i * ELLST;
        float cx = fmaf(ell, dx, sx) + 63.5f;
        float cy = fmaf(ell, dy, sy) + 63.5f;
        float cz = ell * dz + 31.5f;

        bool valid = (cx > -1.0f && cx < 128.0f && cy > -1.0f && cy < 128.0f);
        if (__ballot_sync(0xFFFFFFFFu, valid) == 0u)
            continue;

        unsigned addr = 0xFFFFFFFFu;
        float w0 = 0.f, w1 = 0.f, w2 = 0.f, w3 = 0.f;
        float w4 = 0.f, w5 = 0.f, w6 = 0.f, w7 = 0.f;

        if (valid) {
            float fx = floorf(cx), fy = floorf(cy), fz = floorf(cz);
            int ix = (int)fx, iy = (int)fy, iz = (int)fz;
            float wx = cx - fx, wy = cy - fy, wz = cz - fz;

            int ox = ix & 1, oy = iy & 1;
            int kx = (ix + ox) >> 1, ky = (iy + oy) >> 1;
            int q = oy * 2 + ox;
            addr = (unsigned)(((q * ND + iz) * KB + ky) * KB + kx);

            float t00 = (1.0f - wx) * (1.0f - wy);
            float t01 = wx * (1.0f - wy);
            float t10 = (1.0f - wx) * wy;
            float t11 = wx * wy;
            float vz0 = val * (1.0f - wz);
            float vz1 = val * wz;

            w0 = t00 * vz0; w1 = t01 * vz0; w2 = t10 * vz0; w3 = t11 * vz0;
            w4 = t00 * vz1; w5 = t01 * vz1; w6 = t10 * vz1; w7 = t11 * vz1;
        }

        // segment structure: head lanes + segment end (exclusive) per lane
        unsigned prev = __shfl_up_sync(0xFFFFFFFFu, addr, 1);
        bool head = (lane == 0) || (prev != addr);
        unsigned hb = __ballot_sync(0xFFFFFFFFu, head);
        unsigned above = hb & (0xFFFFFFFEu << lane);            // head bits strictly above
        int next = above ? (__ffs(above) - 1) : 32;             // my segment end
        unsigned below = hb & (0xFFFFFFFFu >> (31 - lane));     // head bits <= lane
        int start = 31 - __clz(below);                          // my segment head

        // 2-step segmented suffix sum (covers 4-lane chunks within a segment)
#pragma unroll
        for (int o = 1; o <= 2; o <<= 1) {
            bool take = (lane + o) < next;
            float t;
            t = __shfl_down_sync(0xFFFFFFFFu, w0, o); if (take) w0 += t;
            t = __shfl_down_sync(0xFFFFFFFFu, w1, o); if (take) w1 += t;
            t = __shfl_down_sync(0xFFFFFFFFu, w2, o); if (take) w2 += t;
            t = __shfl_down_sync(0xFFFFFFFFu, w3, o); if (take) w3 += t;
            t = __shfl_down_sync(0xFFFFFFFFu, w4, o); if (take) w4 += t;
            t = __shfl_down_sync(0xFFFFFFFFu, w5, o); if (take) w5 += t;
            t = __shfl_down_sync(0xFFFFFFFFu, w6, o); if (take) w6 += t;
            t = __shfl_down_sync(0xFFFFFFFFu, w7, o); if (take) w7 += t;
        }

        // one issuer per 4-lane chunk of each segment (handles runs > 4 exactly)
        bool issuer = (((lane - start) & 3) == 0) && (addr != 0xFFFFFFFFu);
        if (issuer) {
            float4* s0 = ((float4*)g_acc) + addr;
            red4(s0,           w0, w1, w2, w3);
            red4(s0 + ZSTRIDE, w4, w5, w6, w7);
        }
    }
}

// ---------------------------------------------------------------------------
// Kernel 3: gather parity accumulators into the output volume
// ---------------------------------------------------------------------------
__global__ __launch_bounds__(128)
void gather_kernel(float* __restrict__ out)
{
    int x  = threadIdx.x;                    // 0..127
    int zy = blockIdx.x;                     // z*NH + y
    int z = zy / NH, y = zy % NH;

    float acc = 0.0f;
    if (z >= ACC_Z0 && z < ACC_Z0 + ACC_ZN) {
#pragma unroll
        for (int oy = 0; oy < 2; oy++) {
            int by = (y + oy) & 1;
            int ky = (y + oy - by) >> 1;
#pragma unroll
            for (int ox = 0; ox < 2; ox++) {
                int bx = (x + ox) & 1;
                int kx = (x + ox - bx) >> 1;
                const float* slot = (const float*)&g_acc[oy * 2 + ox][z][ky][kx];
                acc += __ldg(slot + by * 2 + bx);
            }
        }
    }
    out[zy * NW + x] = acc;
}

// ---------------------------------------------------------------------------
extern "C" void kernel_launch(void* const* d_in, const int* in_sizes, int n_in,
                              void* d_out, int out_size)
{
    const float* x = (const float*)d_in[0];   // [1,1,D,H,W]
    const float* p = (const float*)d_in[1];   // [1,1,A,V,U]
    float* out = (float*)d_out;               // [1,1,D,H,W]

    transpose_kernel<<<dim3(4, 4, ND), dim3(32, 8)>>>(x);
    zero_acc_kernel<<<(ACC_USED_ELEMS + 255) / 256, 256>>>();
    fbp_kernel<<<NA * NV, NU>>>(x, p);
    gather_kernel<<<ND * NH, NW>>>(out);
}